// round 16
// baseline (speedup 1.0000x reference)
#include <cuda_runtime.h>
#include <cuda_fp16.h>
#include <cstdint>
#include <cstddef>

// Problem constants (fixed by the reference)
#define NTT    1024
#define NGRID  2048
#define MAXD   8
#define TROWS  (NTT - MAXD)          // 1016 computed time rows
#define NTILES (TROWS * (NGRID/128)) // 16256 tiles of 128 g-rows

#define NTHREADS 256                 // 8 warps = 2 groups of 4 warps

// fp16 SMEM strides in __half units. Row = 128 halves data + 8 pad = 136.
// Word index = row*68 + k/2; per ldmatrix 8x8-matrix phase the 8 consecutive
// rows hit word-groups 68i mod 32 = 4i -> all 32 banks once -> conflict-free.
#define A_STRIDE 136
#define W_STRIDE 136
#define ROW_BYTES (A_STRIDE*2)       // 272
// Layout: W1 | W2 | A (each 128*136 halves) then fp32 b1,b2,wout,yts
#define SMEM_HALVES (3*128*136)
#define SMEM_BYTES  (SMEM_HALVES*2 + 4*128*4)   // 104,448 + 2,048 = 106,496 B

// Named barrier per 4-warp group (ids 1..2; 0 reserved for __syncthreads)
#define BAR_GROUP(id) asm volatile("bar.sync %0, 128;" :: "r"(id) : "memory")

// tanh(x) = 1 - 2/(exp(2x)+1) via MUFU ex2 + MUFU rcp (~1e-7 rel err)
__device__ __forceinline__ float fast_tanh(float x) {
    float e;
    asm("ex2.approx.f32 %0, %1;" : "=f"(e) : "f"(x * 2.885390081777927f)); // 2*log2(e)
    float r;
    asm("rcp.approx.f32 %0, %1;" : "=f"(r) : "f"(e + 1.0f));
    return fmaf(-2.0f, r, 1.0f);
}

// m16n8k16 fp16 MMA, fp32 accumulate
__device__ __forceinline__ void mma_f16(float d[4],
                                        uint32_t a0, uint32_t a1, uint32_t a2, uint32_t a3,
                                        uint32_t b0, uint32_t b1) {
    asm volatile(
        "mma.sync.aligned.m16n8k16.row.col.f32.f16.f16.f32 "
        "{%0,%1,%2,%3}, {%4,%5,%6,%7}, {%8,%9}, {%0,%1,%2,%3};"
        : "+f"(d[0]), "+f"(d[1]), "+f"(d[2]), "+f"(d[3])
        : "r"(a0), "r"(a1), "r"(a2), "r"(a3), "r"(b0), "r"(b1));
}

// ldmatrix x4: one instruction loads 4 8x8 fp16 matrices
__device__ __forceinline__ void ldsm4(uint32_t r[4], uint32_t addr) {
    asm volatile("ldmatrix.sync.aligned.m8n8.x4.shared.b16 {%0,%1,%2,%3}, [%4];"
        : "=r"(r[0]), "=r"(r[1]), "=r"(r[2]), "=r"(r[3]) : "r"(addr));
}

__device__ __forceinline__ uint32_t smem_u32(const void* p) {
    uint32_t a;
    asm("{ .reg .u64 t; cvta.to.shared.u64 t, %1; cvt.u32.u64 %0, t; }"
        : "=r"(a) : "l"(p));
    return a;
}

// ---------------------------------------------------------------------------
// 32x64 warp sub-tile of the 128x128x128 fp16 GEMM via ldmatrix.
// 192 B of fragments per MMA (vs 256 at 32x32): 6 LDSM.x4 + 16 HMMA per K-step.
//   Aaddr: rows mb + (sel&1)*8 + p, k-offset (sel>>1)*8 -> m16n8k16 A order.
//   Baddr: rows nb + sel*8 + p -> r[sel] = b0[nt=sel]; +16B = b1 (k-high);
//          +32*ROW_BYTES = col-half 2 (nt=4..7).
// ---------------------------------------------------------------------------
__device__ __forceinline__ void gemm_tile(uint32_t Aaddr, uint32_t Baddr,
                                          float acc[2][8][4]) {
    #pragma unroll
    for (int ks = 0; ks < 8; ks++) {
        uint32_t p0[4], p1[4], q0[4], q1[4], a0[4], a1[4];
        ldsm4(p0, Baddr + ks*32);                        // cols +0..31,  k-low
        ldsm4(p1, Baddr + ks*32 + 16);                   // cols +0..31,  k-high
        ldsm4(q0, Baddr + 32*ROW_BYTES + ks*32);         // cols +32..63, k-low
        ldsm4(q1, Baddr + 32*ROW_BYTES + ks*32 + 16);    // cols +32..63, k-high
        ldsm4(a0, Aaddr + ks*32);                        // rows +0..15
        #pragma unroll
        for (int nt = 0; nt < 4; nt++) {
            mma_f16(acc[0][nt],   a0[0], a0[1], a0[2], a0[3], p0[nt], p1[nt]);
            mma_f16(acc[0][nt+4], a0[0], a0[1], a0[2], a0[3], q0[nt], q1[nt]);
        }
        ldsm4(a1, Aaddr + 16*ROW_BYTES + ks*32);         // rows +16..31
        #pragma unroll
        for (int nt = 0; nt < 4; nt++) {
            mma_f16(acc[1][nt],   a1[0], a1[1], a1[2], a1[3], p0[nt], p1[nt]);
            mma_f16(acc[1][nt+4], a1[0], a1[1], a1[2], a1[3], q0[nt], q1[nt]);
        }
    }
}

// Group-local feature prefetch: 64-row slab, 16 LDG.128 per thread
// (128 threads x 2 float4 per 4KB delay slab x 8 delays). Fully coalesced.
__device__ __forceinline__ void load_feat(const float* __restrict__ x, int t,
                                          int gbase, int wtid, float4 pf[16]) {
    #pragma unroll
    for (int j = 0; j < 8; j++) {
        const float* base = x + ((size_t)(t - 1 - j) * NGRID + gbase) * 16;
        pf[2*j]   = *(const float4*)(base + (size_t)wtid * 4);
        pf[2*j+1] = *(const float4*)(base + (size_t)(wtid + 128) * 4);
    }
}

// ---------------------------------------------------------------------------
// SINGLE persistent kernel, 256 threads = 2 INDEPENDENT 4-warp pipelines.
// Group wr owns rows 64*wr..64*wr+63 (feat commit, GEMM A-reads, epi1 writes,
// GEMM2 reads, yts, output). Warps within a group: 2 row-halves x 2 col-halves
// of 32x64 tiles. SMSP k hosts warps k (group 0) and k+4 (group 1) -> the two
// groups' phases mix on every scheduler (tensor vs LSU vs MUFU).
// ---------------------------------------------------------------------------
__global__ __launch_bounds__(NTHREADS, 1)
void narx_main(const float* __restrict__ x,
               const float* __restrict__ W_in,  const float* __restrict__ b_in,
               const float* __restrict__ W_ih,  const float* __restrict__ b_ih,
               const float* __restrict__ b_hh,  const float* __restrict__ W_out,
               const float* __restrict__ b_out, float* __restrict__ out) {
    extern __shared__ __half smh[];
    __half* W1s = smh;                      // [h=128][k] stride W_STRIDE (folded W_in)
    __half* W2s = W1s + 128*W_STRIDE;       // [h=128][k] = W_ih (row-major [n][k])
    __half* As  = W2s + 128*W_STRIDE;       // [row=128][k] feat / h_in tile
    float* b1s   = (float*)(smh + SMEM_HALVES);
    float* b2s   = b1s + 128;
    float* wouts = b2s + 128;
    float* yts   = wouts + 128;

    const int tid  = threadIdx.x;
    const int warp = tid >> 5;
    const int lane = tid & 31;
    const int gid  = lane >> 2;   // group id 0..7 (within warp)
    const int cq   = lane & 3;    // quad 0..3
    const int wr   = warp >> 2;          // pipeline group 0..1
    const int w2   = warp & 3;           // warp within group
    const int mb   = wr*64 + (w2 >> 1)*32;  // row base: slab + row-half
    const int nb   = (w2 & 1)*64;           // col base: 0 or 64
    const int wtid = tid & 127;          // thread index within group
    const int barid = 1 + wr;            // named barrier id

    // ldmatrix per-thread address bases
    const int p   = lane & 7;
    const int sel = lane >> 3;
    const uint32_t W1b = smem_u32(W1s), W2b = smem_u32(W2s), Asb = smem_u32(As);
    const uint32_t Aaddr  = Asb + (uint32_t)(mb + (sel & 1)*8 + p) * ROW_BYTES
                                + (uint32_t)(sel >> 1) * 16;
    const uint32_t B1addr = W1b + (uint32_t)(nb + sel*8 + p) * ROW_BYTES;
    const uint32_t B2addr = W2b + (uint32_t)(nb + sel*8 + p) * ROW_BYTES;

    // ---- head passthrough: out[0:8, :, 0] = x[0:8, :, 15] (striped) ----
    for (int i = blockIdx.x * NTHREADS + tid; i < MAXD * NGRID; i += gridDim.x * NTHREADS)
        out[i] = x[(size_t)i * 16 + 15];

    // ---- per-CTA prep: fold W_in (128x144, dup offset -1) into W1s[h][k],
    //      copy W_ih into W2s[h][k]; fp16-round. L2-broadcast reads. ----
    for (int i = tid; i < 128*128; i += NTHREADS) {
        int h = i >> 7, k = i & 127;
        int d = (k >> 4) + 1;   // delay 1..8
        int c = k & 15;         // channel 0..15 (15 == yf channel)
        int j = 9 - d;          // 1..8
        float v;
        if (c < 15) {
            v = W_in[h*144 + j*15 + c];
            if (d == 1) v += W_in[h*144 + c];          // duplicate offset -1 (j=0)
        } else {
            v = W_in[h*144 + 135 + j];
            if (d == 1) v += W_in[h*144 + 135];
        }
        W1s[h*W_STRIDE + k] = __float2half_rn(v);
        W2s[h*W_STRIDE + k] = __float2half_rn(W_ih[h*128 + k]);
    }
    if (tid < 128) {
        b1s[tid]   = b_in[tid];
        b2s[tid]   = b_ih[tid] + b_hh[tid];
        wouts[tid] = W_out[tid];
        yts[tid]   = 0.f;
    }

    const float bout = b_out[0];
    // group-local feat-commit: thread covers slab float4 #wtid and #wtid+128
    // (rows wtid>>2 and 32+(wtid>>2) of the 64-row slab), channel block cc.
    const int cc = (wtid & 3) * 4;
    __half* Ac0 = As + (wr*64 + (wtid >> 2)) * A_STRIDE + cc;
    __half* Ac1 = Ac0 + 32*A_STRIDE;

    // Prologue: load + commit first tile's feature slab (group-local rows)
    int tile = blockIdx.x;
    float4 pf[16];
    if (tile < NTILES) {
        load_feat(x, MAXD + (tile >> 4), (tile & 15) * 128 + wr*64, wtid, pf);
        #pragma unroll
        for (int j = 0; j < 8; j++) {
            __half2 l0 = __floats2half2_rn(pf[2*j].x,   pf[2*j].y);
            __half2 h0 = __floats2half2_rn(pf[2*j].z,   pf[2*j].w);
            __half2 l1 = __floats2half2_rn(pf[2*j+1].x, pf[2*j+1].y);
            __half2 h1 = __floats2half2_rn(pf[2*j+1].z, pf[2*j+1].w);
            uint2 k0; k0.x = *(uint32_t*)&l0; k0.y = *(uint32_t*)&h0;
            uint2 k1; k1.x = *(uint32_t*)&l1; k1.y = *(uint32_t*)&h1;
            *(uint2*)(Ac0 + j*16) = k0;
            *(uint2*)(Ac1 + j*16) = k1;
        }
    }
    __syncthreads();   // feat0 + weights + yts ready (only CTA-wide sync)

    int prev_t = -1, prev_g0 = 0;

    for (; tile < NTILES; tile += gridDim.x) {
        const int t  = MAXD + (tile >> 4);
        const int g0 = (tile & 15) * 128;

        // Prefetch next tile's feature slab (consumed at end of iteration)
        const int nxt = tile + gridDim.x;
        if (nxt < NTILES)
            load_feat(x, MAXD + (nxt >> 4), (nxt & 15) * 128 + wr*64, wtid, pf);

        // ---- GEMM1: h_pre_in = feat @ Wc^T  (overlaps prev tile's epi2) ----
        float acc[2][8][4];
        #pragma unroll
        for (int mt = 0; mt < 2; mt++)
            #pragma unroll
            for (int nt = 0; nt < 8; nt++)
                #pragma unroll
                for (int q = 0; q < 4; q++) acc[mt][nt][q] = 0.f;

        gemm_tile(Aaddr, B1addr, acc);
        BAR_GROUP(barid);  // slab feat reads done; group's epi2 atomics visible

        // Deferred output store for previous tile (group slab), re-zero yts
        if (wtid < 64) {
            if (prev_t >= 0)
                out[(size_t)prev_t * NGRID + prev_g0 + wr*64 + wtid] = yts[wr*64 + wtid] + bout;
            yts[wr*64 + wtid] = 0.f;
        }

        // Epilogue1: relu(.+b_in) -> fp16, write h_in back into slab rows.
        #pragma unroll
        for (int mt = 0; mt < 2; mt++) {
            int r = mb + mt*16 + gid;
            #pragma unroll
            for (int nt = 0; nt < 8; nt++) {
                int col = nb + nt*8 + 2*cq;
                float bb0 = b1s[col], bb1 = b1s[col+1];
                __half2 v0 = __floats2half2_rn(fmaxf(acc[mt][nt][0] + bb0, 0.f),
                                               fmaxf(acc[mt][nt][1] + bb1, 0.f));
                __half2 v1 = __floats2half2_rn(fmaxf(acc[mt][nt][2] + bb0, 0.f),
                                               fmaxf(acc[mt][nt][3] + bb1, 0.f));
                *(__half2*)(As + (size_t)r*A_STRIDE + col)     = v0;
                *(__half2*)(As + (size_t)(r+8)*A_STRIDE + col) = v1;
            }
        }
        BAR_GROUP(barid);  // slab h_in ready (all 128 cols from group's warps)

        // ---- GEMM2: h_pre = h_in @ W_ih^T ----
        #pragma unroll
        for (int mt = 0; mt < 2; mt++)
            #pragma unroll
            for (int nt = 0; nt < 8; nt++)
                #pragma unroll
                for (int q = 0; q < 4; q++) acc[mt][nt][q] = 0.f;

        gemm_tile(Aaddr, B2addr, acc);
        BAR_GROUP(barid);  // slab h_in reads done -> slab rows free

        // Commit NEXT tile's feature slab (so next GEMM1 starts right after
        // the group barrier, concurrent with this tile's epi2)
        if (nxt < NTILES) {
            #pragma unroll
            for (int j = 0; j < 8; j++) {
                __half2 l0 = __floats2half2_rn(pf[2*j].x,   pf[2*j].y);
                __half2 h0 = __floats2half2_rn(pf[2*j].z,   pf[2*j].w);
                __half2 l1 = __floats2half2_rn(pf[2*j+1].x, pf[2*j+1].y);
                __half2 h1 = __floats2half2_rn(pf[2*j+1].z, pf[2*j+1].w);
                uint2 k0; k0.x = *(uint32_t*)&l0; k0.y = *(uint32_t*)&h0;
                uint2 k1; k1.x = *(uint32_t*)&l1; k1.y = *(uint32_t*)&h1;
                *(uint2*)(Ac0 + j*16) = k0;
                *(uint2*)(Ac1 + j*16) = k1;
            }
        }
        BAR_GROUP(barid);  // next feat slab ready

        // Epilogue2: tanh(.+b2) (MUFU), fused W_out dot, shfl + shared-atomic
        // reduce into group's yts rows. NO barrier after: flow into next GEMM1.
        #pragma unroll
        for (int mt = 0; mt < 2; mt++) {
            float p0 = 0.f, p1 = 0.f;
            #pragma unroll
            for (int nt = 0; nt < 8; nt++) {
                int col = nb + nt*8 + 2*cq;
                float w0 = wouts[col], w1 = wouts[col+1];
                float bb0 = b2s[col], bb1 = b2s[col+1];
                p0 += fast_tanh(acc[mt][nt][0] + bb0) * w0
                    + fast_tanh(acc[mt][nt][1] + bb1) * w1;
                p1 += fast_tanh(acc[mt][nt][2] + bb0) * w0
                    + fast_tanh(acc[mt][nt][3] + bb1) * w1;
            }
            p0 += __shfl_xor_sync(0xffffffffu, p0, 1);
            p0 += __shfl_xor_sync(0xffffffffu, p0, 2);
            p1 += __shfl_xor_sync(0xffffffffu, p1, 1);
            p1 += __shfl_xor_sync(0xffffffffu, p1, 2);
            if (cq == 0) {
                int r = mb + mt*16 + gid;
                atomicAdd(&yts[r],     p0);   // 2 col-half partials per row
                atomicAdd(&yts[r + 8], p1);
            }
        }

        prev_t = t; prev_g0 = g0;
    }

    // Drain: store the last tile's output slab
    BAR_GROUP(barid);
    if (prev_t >= 0 && wtid < 64)
        out[(size_t)prev_t * NGRID + prev_g0 + wr*64 + wtid] = yts[wr*64 + wtid] + bout;
}

extern "C" void kernel_launch(void* const* d_in, const int* in_sizes, int n_in,
                              void* d_out, int out_size) {
    const float* x     = (const float*)d_in[0];
    const float* W_in  = (const float*)d_in[1];
    const float* b_in  = (const float*)d_in[2];
    const float* W_ih  = (const float*)d_in[3];
    const float* b_ih  = (const float*)d_in[4];
    /* d_in[5] = W_hh — dead in the reference (only b_hh is used) */
    const float* b_hh  = (const float*)d_in[6];
    const float* W_out = (const float*)d_in[7];
    const float* b_out = (const float*)d_in[8];
    float* out = (float*)d_out;

    cudaFuncSetAttribute(narx_main, cudaFuncAttributeMaxDynamicSharedMemorySize, SMEM_BYTES);
    int dev = 0, sms = 0;
    cudaGetDevice(&dev);
    cudaDeviceGetAttribute(&sms, cudaDevAttrMultiProcessorCount, dev);
    if (sms <= 0) sms = 148;

    narx_main<<<sms, NTHREADS, SMEM_BYTES>>>(x, W_in, b_in, W_ih, b_ih, b_hh,
                                             W_out, b_out, out);
}

// round 17
// speedup vs baseline: 1.2491x; 1.2491x over previous
#include <cuda_runtime.h>
#include <cuda_fp16.h>
#include <cstdint>
#include <cstddef>

// Problem constants (fixed by the reference)
#define NTT    1024
#define NGRID  2048
#define MAXD   8
#define TSTRIP (NTT - MAXD)          // 1016 tiles per g-strip
#define NTILES (TSTRIP * (NGRID/128))// 16256 tiles of 128 g-rows

#define NTHREADS 512                 // 16 warps = 2 groups of 8 warps

// fp16 SMEM strides in __half units. Row = 128 halves data + 8 pad = 136.
// Word index = row*68 + k/2; per ldmatrix 8x8-matrix phase the 8 consecutive
// rows hit word-groups 4i + const mod 32 -> all 32 banks once -> conflict-free.
#define A_STRIDE 136
#define ROW_BYTES (A_STRIDE*2)       // 272
#define TILE_HALVES (128*A_STRIDE)   // 17408

// SMEM layout (halves): W1 | W2 | RING0 | RING1 | HIN0 | HIN1, then fp32 tail
#define W1_OFF   0
#define W2_OFF   (1*TILE_HALVES)
#define RING_OFF (2*TILE_HALVES)     // + wr*TILE_HALVES
#define HIN_OFF  (4*TILE_HALVES)     // + wr*TILE_HALVES
#define SMEM_HALVES (6*TILE_HALVES)
#define SMEM_BYTES (SMEM_HALVES*2 + 3*128*4 + 256*4)   // 211,456 B (max 227KB)

// Named barrier per 8-warp group (ids 1..2; 0 reserved for __syncthreads)
#define BAR_GROUP(id) asm volatile("bar.sync %0, 256;" :: "r"(id) : "memory")

// tanh(x) = 1 - 2/(exp(2x)+1) via MUFU ex2 + MUFU rcp (~1e-7 rel err)
__device__ __forceinline__ float fast_tanh(float x) {
    float e;
    asm("ex2.approx.f32 %0, %1;" : "=f"(e) : "f"(x * 2.885390081777927f)); // 2*log2(e)
    float r;
    asm("rcp.approx.f32 %0, %1;" : "=f"(r) : "f"(e + 1.0f));
    return fmaf(-2.0f, r, 1.0f);
}

// m16n8k16 fp16 MMA, fp32 accumulate
__device__ __forceinline__ void mma_f16(float d[4],
                                        uint32_t a0, uint32_t a1, uint32_t a2, uint32_t a3,
                                        uint32_t b0, uint32_t b1) {
    asm volatile(
        "mma.sync.aligned.m16n8k16.row.col.f32.f16.f16.f32 "
        "{%0,%1,%2,%3}, {%4,%5,%6,%7}, {%8,%9}, {%0,%1,%2,%3};"
        : "+f"(d[0]), "+f"(d[1]), "+f"(d[2]), "+f"(d[3])
        : "r"(a0), "r"(a1), "r"(a2), "r"(a3), "r"(b0), "r"(b1));
}

// ldmatrix x4: one instruction loads 4 8x8 fp16 matrices
__device__ __forceinline__ void ldsm4(uint32_t r[4], uint32_t addr) {
    asm volatile("ldmatrix.sync.aligned.m8n8.x4.shared.b16 {%0,%1,%2,%3}, [%4];"
        : "=r"(r[0]), "=r"(r[1]), "=r"(r[2]), "=r"(r[3]) : "r"(addr));
}

__device__ __forceinline__ uint32_t smem_u32(const void* p) {
    uint32_t a;
    asm("{ .reg .u64 t; cvta.to.shared.u64 t, %1; cvt.u32.u64 %0, t; }"
        : "=r"(a) : "l"(p));
    return a;
}

// ---------------------------------------------------------------------------
// 32x64 warp sub-tile of a 128x128x128 fp16 GEMM via ldmatrix (192 B/MMA).
// RING=true: A k-chunk ks lives at ring slot (t1-ks)&7 (one K-step == one
// delay slab, so slot lookup is exact). RING=false (h_in): identity mapping.
// 6 LDSM.x4 + 16 HMMA per K-step.
// ---------------------------------------------------------------------------
template<bool RING>
__device__ __forceinline__ void gemm_tile(uint32_t Aaddr, uint32_t Baddr,
                                          int t1, float acc[2][8][4]) {
    #pragma unroll
    for (int ks = 0; ks < 8; ks++) {
        const uint32_t aoff = RING ? (uint32_t)(((t1 - ks) & 7) * 32)
                                   : (uint32_t)(ks * 32);
        uint32_t p0[4], p1[4], q0[4], q1[4], a0[4], a1[4];
        ldsm4(p0, Baddr + ks*32);                        // cols nb+0..31,  k-lo
        ldsm4(p1, Baddr + ks*32 + 16);                   // cols nb+0..31,  k-hi
        ldsm4(q0, Baddr + 32*ROW_BYTES + ks*32);         // cols nb+32..63, k-lo
        ldsm4(q1, Baddr + 32*ROW_BYTES + ks*32 + 16);    // cols nb+32..63, k-hi
        ldsm4(a0, Aaddr + aoff);                         // rows mb+0..15
        #pragma unroll
        for (int nt = 0; nt < 4; nt++) {
            mma_f16(acc[0][nt],   a0[0], a0[1], a0[2], a0[3], p0[nt], p1[nt]);
            mma_f16(acc[0][nt+4], a0[0], a0[1], a0[2], a0[3], q0[nt], q1[nt]);
        }
        ldsm4(a1, Aaddr + 16*ROW_BYTES + aoff);          // rows mb+16..31
        #pragma unroll
        for (int nt = 0; nt < 4; nt++) {
            mma_f16(acc[1][nt],   a1[0], a1[1], a1[2], a1[3], p0[nt], p1[nt]);
            mma_f16(acc[1][nt+4], a1[0], a1[1], a1[2], a1[3], q0[nt], q1[nt]);
        }
    }
}

// Commit one 8KB slab (held in pf[2]) into ring slot: 2 uint2 stores/thread.
__device__ __forceinline__ void commit_slab(__half* ring, int slot, int wtid,
                                            const float4 pf[2]) {
    #pragma unroll
    for (int i = 0; i < 2; i++) {
        const int idx = wtid + i*256;     // float4 index 0..511
        const int row = idx >> 2;
        const int c4  = (idx & 3) * 4;
        __half2 lo = __floats2half2_rn(pf[i].x, pf[i].y);
        __half2 hi = __floats2half2_rn(pf[i].z, pf[i].w);
        uint2 pk; pk.x = *(uint32_t*)&lo; pk.y = *(uint32_t*)&hi;
        *(uint2*)(ring + row*A_STRIDE + slot*16 + c4) = pk;
    }
}

// Full ring fill for tile t (8 slabs x[t-1-j] -> slot (t-1-j)&7). Rare.
__device__ __forceinline__ void full_load(const float* __restrict__ x, int t,
                                          int g0, __half* ring, int wtid) {
    #pragma unroll
    for (int j = 0; j < 8; j++) {
        const int slot = (t - 1 - j) & 7;
        const float* base = x + ((size_t)(t - 1 - j) * NGRID + g0) * 16;
        float4 pf[2];
        pf[0] = *(const float4*)(base + (size_t)wtid * 4);
        pf[1] = *(const float4*)(base + (size_t)(wtid + 256) * 4);
        commit_slab(ring, slot, wtid, pf);
    }
}

// ---------------------------------------------------------------------------
// SINGLE persistent kernel, 512 threads = 2 INDEPENDENT 8-warp pipelines.
// Each group owns a full 128x128 tile sequence over a CONTIGUOUS t-strip:
// per tile only ONE new 8KB delay slab is loaded into the group's SMEM ring
// (8x less x traffic + tiny prefetch register cost). h_in uses its own
// buffer so the ring survives. Warps: 4 row-slabs x 2 col-halves of 32x64
// tiles (192 B/MMA, -25% LDSM vs 32x32). SMSP k hosts 2 warps of EACH group
// -> phases mix on every scheduler.
// ---------------------------------------------------------------------------
__global__ __launch_bounds__(NTHREADS, 1)
void narx_main(const float* __restrict__ x,
               const float* __restrict__ W_in,  const float* __restrict__ b_in,
               const float* __restrict__ W_ih,  const float* __restrict__ b_ih,
               const float* __restrict__ b_hh,  const float* __restrict__ W_out,
               const float* __restrict__ b_out, float* __restrict__ out) {
    extern __shared__ __half smh[];
    __half* W1s = smh + W1_OFF;             // [h=128][k] (folded W_in)
    __half* W2s = smh + W2_OFF;             // [h=128][k] = W_ih
    float* b1s   = (float*)(smh + SMEM_HALVES);
    float* b2s   = b1s + 128;
    float* wouts = b2s + 128;
    float* ytsA  = wouts + 128;             // [2][128]

    const int tid  = threadIdx.x;
    const int warp = tid >> 5;
    const int lane = tid & 31;
    const int gid  = lane >> 2;   // group id 0..7 (within warp)
    const int cq   = lane & 3;    // quad 0..3
    const int wr   = warp >> 3;          // pipeline group 0..1
    const int w8   = warp & 7;           // warp within group
    const int mb   = (w8 >> 1) * 32;     // row slab: 0,32,64,96
    const int nb   = (w8 & 1) * 64;      // col half: 0 or 64
    const int wtid = tid & 255;          // thread index within group
    const int barid = 1 + wr;            // named barrier id

    __half* ringG = smh + RING_OFF + wr*TILE_HALVES;
    __half* hinG  = smh + HIN_OFF  + wr*TILE_HALVES;
    float*  yts_g = ytsA + wr*128;

    // ldmatrix per-thread address bases
    const int p   = lane & 7;
    const int sel = lane >> 3;
    const uint32_t rowAoff = (uint32_t)(mb + (sel & 1)*8 + p) * ROW_BYTES
                           + (uint32_t)(sel >> 1) * 16;
    const uint32_t AaddrR = smem_u32(ringG) + rowAoff;
    const uint32_t AaddrH = smem_u32(hinG)  + rowAoff;
    const uint32_t rowBoff = (uint32_t)(nb + sel*8 + p) * ROW_BYTES;
    const uint32_t B1addr = smem_u32(W1s) + rowBoff;
    const uint32_t B2addr = smem_u32(W2s) + rowBoff;

    // ---- head passthrough: out[0:8, :, 0] = x[0:8, :, 15] (striped) ----
    for (int i = blockIdx.x * NTHREADS + tid; i < MAXD * NGRID; i += gridDim.x * NTHREADS)
        out[i] = x[(size_t)i * 16 + 15];

    // ---- per-CTA prep: fold W_in (128x144, dup offset -1) into W1s[h][k],
    //      copy W_ih into W2s[h][k]; fp16-round. L2-broadcast reads. ----
    for (int i = tid; i < 128*128; i += NTHREADS) {
        int h = i >> 7, k = i & 127;
        int d = (k >> 4) + 1;   // delay 1..8
        int c = k & 15;         // channel 0..15 (15 == yf channel)
        int j = 9 - d;          // 1..8
        float v;
        if (c < 15) {
            v = W_in[h*144 + j*15 + c];
            if (d == 1) v += W_in[h*144 + c];          // duplicate offset -1 (j=0)
        } else {
            v = W_in[h*144 + 135 + j];
            if (d == 1) v += W_in[h*144 + 135];
        }
        W1s[h*A_STRIDE + k] = __float2half_rn(v);
        W2s[h*A_STRIDE + k] = __float2half_rn(W_ih[h*128 + k]);
    }
    if (tid < 128) {
        b1s[tid]   = b_in[tid];
        b2s[tid]   = b_ih[tid] + b_hh[tid];
        wouts[tid] = W_out[tid];
    }
    if (tid < 256) ytsA[tid] = 0.f;
    __syncthreads();   // weights + yts ready (only CTA-wide sync)

    const float bout = b_out[0];

    // ---- chunk assignment: pipeline pid owns tiles [start, end) in
    //      g-major/t-minor order (li = g*TSTRIP + (t-MAXD)) ----
    const int P   = gridDim.x * 2;
    const int CH  = (NTILES + P - 1) / P;
    const int pid = blockIdx.x * 2 + wr;
    const int start = pid * CH;
    const int end   = min(start + CH, NTILES);

    int g = 0, toff = 0;
    if (start < end) {
        g    = start / TSTRIP;
        toff = start - g * TSTRIP;
        full_load(x, MAXD + toff, g * 128, ringG, wtid);   // prologue ring fill
    }

    int prev_t = -1, prev_g0 = 0;

    for (int li = start; li < end; li++) {
        const int t  = MAXD + toff;
        const int g0 = g * 128;
        const bool last = (li + 1 == end);
        const bool fresh_next = (toff + 1 == TSTRIP);

        // Prefetch next tile's ONE new slab (x[t] at same g0); hidden by GEMMs
        float4 pf[2];
        if (!last && !fresh_next) {
            const float* base = x + ((size_t)t * NGRID + g0) * 16;
            pf[0] = *(const float4*)(base + (size_t)wtid * 4);
            pf[1] = *(const float4*)(base + (size_t)(wtid + 256) * 4);
        }

        BAR_GROUP(barid);  // ring commit done; prev epi2 atomics visible

        // Deferred output store for previous tile, re-zero yts
        if (wtid < 128) {
            if (prev_t >= 0)
                out[(size_t)prev_t * NGRID + prev_g0 + wtid] = yts_g[wtid] + bout;
            yts_g[wtid] = 0.f;
        }

        // ---- GEMM1: h_pre_in = feat(ring) @ Wc^T ----
        float acc[2][8][4];
        #pragma unroll
        for (int mt = 0; mt < 2; mt++)
            #pragma unroll
            for (int nt = 0; nt < 8; nt++)
                #pragma unroll
                for (int q = 0; q < 4; q++) acc[mt][nt][q] = 0.f;

        gemm_tile<true>(AaddrR, B1addr, t - 1, acc);

        // Epilogue1: relu(.+b_in) -> fp16 into the h_in buffer (ring intact)
        #pragma unroll
        for (int mt = 0; mt < 2; mt++) {
            int r = mb + mt*16 + gid;
            #pragma unroll
            for (int nt = 0; nt < 8; nt++) {
                int col = nb + nt*8 + 2*cq;
                float bb0 = b1s[col], bb1 = b1s[col+1];
                __half2 v0 = __floats2half2_rn(fmaxf(acc[mt][nt][0] + bb0, 0.f),
                                               fmaxf(acc[mt][nt][1] + bb1, 0.f));
                __half2 v1 = __floats2half2_rn(fmaxf(acc[mt][nt][2] + bb0, 0.f),
                                               fmaxf(acc[mt][nt][3] + bb1, 0.f));
                *(__half2*)(hinG + (size_t)r*A_STRIDE + col)     = v0;
                *(__half2*)(hinG + (size_t)(r+8)*A_STRIDE + col) = v1;
            }
        }
        BAR_GROUP(barid);  // h_in ready; ring reads done (commit safe later)

        // ---- GEMM2: h_pre = h_in @ W_ih^T ----
        #pragma unroll
        for (int mt = 0; mt < 2; mt++)
            #pragma unroll
            for (int nt = 0; nt < 8; nt++)
                #pragma unroll
                for (int q = 0; q < 4; q++) acc[mt][nt][q] = 0.f;

        gemm_tile<false>(AaddrH, B2addr, 0, acc);
        BAR_GROUP(barid);  // h_in reads done -> next epi1 safe

        // Epilogue2: tanh(.+b2) (MUFU), fused W_out dot, shfl + shared-atomic
        // reduce into group's yts. No barrier after: flows into commit+GEMM1.
        #pragma unroll
        for (int mt = 0; mt < 2; mt++) {
            float p0 = 0.f, p1 = 0.f;
            #pragma unroll
            for (int nt = 0; nt < 8; nt++) {
                int col = nb + nt*8 + 2*cq;
                float w0 = wouts[col], w1 = wouts[col+1];
                float bb0 = b2s[col], bb1 = b2s[col+1];
                p0 += fast_tanh(acc[mt][nt][0] + bb0) * w0
                    + fast_tanh(acc[mt][nt][1] + bb1) * w1;
                p1 += fast_tanh(acc[mt][nt][2] + bb0) * w0
                    + fast_tanh(acc[mt][nt][3] + bb1) * w1;
            }
            p0 += __shfl_xor_sync(0xffffffffu, p0, 1);
            p0 += __shfl_xor_sync(0xffffffffu, p0, 2);
            p1 += __shfl_xor_sync(0xffffffffu, p1, 1);
            p1 += __shfl_xor_sync(0xffffffffu, p1, 2);
            if (cq == 0) {
                int r = mb + mt*16 + gid;
                atomicAdd(&yts_g[r],     p0);   // 2 col-half partials per row
                atomicAdd(&yts_g[r + 8], p1);
            }
        }

        // Ring update for the next tile (ordered before its GEMM1 by bar A)
        if (!last) {
            if (fresh_next) full_load(x, MAXD, (g + 1) * 128, ringG, wtid);
            else            commit_slab(ringG, t & 7, wtid, pf);
        }

        prev_t = t; prev_g0 = g0;
        if (++toff == TSTRIP) { toff = 0; g++; }
    }

    // Drain: store the last tile's output
    BAR_GROUP(barid);
    if (prev_t >= 0 && wtid < 128)
        out[(size_t)prev_t * NGRID + prev_g0 + wtid] = yts_g[wtid] + bout;
}

extern "C" void kernel_launch(void* const* d_in, const int* in_sizes, int n_in,
                              void* d_out, int out_size) {
    const float* x     = (const float*)d_in[0];
    const float* W_in  = (const float*)d_in[1];
    const float* b_in  = (const float*)d_in[2];
    const float* W_ih  = (const float*)d_in[3];
    const float* b_ih  = (const float*)d_in[4];
    /* d_in[5] = W_hh — dead in the reference (only b_hh is used) */
    const float* b_hh  = (const float*)d_in[6];
    const float* W_out = (const float*)d_in[7];
    const float* b_out = (const float*)d_in[8];
    float* out = (float*)d_out;

    cudaFuncSetAttribute(narx_main, cudaFuncAttributeMaxDynamicSharedMemorySize, SMEM_BYTES);
    int dev = 0, sms = 0;
    cudaGetDevice(&dev);
    cudaDeviceGetAttribute(&sms, cudaDevAttrMultiProcessorCount, dev);
    if (sms <= 0) sms = 148;

    narx_main<<<sms, NTHREADS, SMEM_BYTES>>>(x, W_in, b_in, W_ih, b_ih, b_hh,
                                             W_out, b_out, out);
}